// round 4
// baseline (speedup 1.0000x reference)
#include <cuda_runtime.h>
#include <cstdint>

#define B_   2
#define C_   64
#define D_   8
#define H_   128
#define W_   128
#define V_   (D_*H_*W_)      // 131072
#define L_   101
#define NCV  4
#define KD_  64
#define NLM_ 20
#define N_   120
#define NP_  60              // n-pairs
#define EPS_ 1e-3f

// output layout (reference tuple order, flattened)
#define OFF_X     0L
#define NUM_X     (2L*64*8*128*128)          // 16777216
#define OFF_INST  (OFF_X + NUM_X)            // 16777216
#define NUM_INST  (2L*120*64)                // 15360
#define OFF_MASKS (OFF_INST + NUM_INST)      // 16792576
#define NUM_MASKS (2L*120*131072)            // 31457280
#define OFF_PK    (OFF_MASKS + NUM_MASKS)    // 48249856

typedef unsigned long long u64p;   // packed f32x2 carrier

// ---------------- device scratch (no allocations allowed) ----------------
__device__ float  g_bufA[B_*C_*V_];
__device__ float  g_bufB[B_*C_*V_];
__device__ float  g_pw[NCV*C_*9*C_];          // packed weights [l][ci][k][co]
__device__ float  g_sums[B_*L_*C_];
__device__ int    g_counts[B_*L_];
__device__ double g_sum1, g_sum2;
__device__ float  g_mu2, g_scale2, g_beta2;
__device__ float2 g_kpack[B_*NP_*KD_];        // (K[2np][kd], K[2np+1][kd])

// ---------------- packed f32x2 helpers (Blackwell) ----------------
__device__ __forceinline__ u64p ffma2(u64p a, u64p b, u64p c) {
    u64p d;
    asm("fma.rn.f32x2 %0, %1, %2, %3;" : "=l"(d) : "l"(a), "l"(b), "l"(c));
    return d;
}
__device__ __forceinline__ u64p pack2(float x) {
    u64p d; unsigned u = __float_as_uint(x);
    asm("mov.b64 %0, {%1, %1};" : "=l"(d) : "r"(u));
    return d;
}
__device__ __forceinline__ void unpack2(u64p v, float& lo, float& hi) {
    unsigned a, b;
    asm("mov.b64 {%0, %1}, %2;" : "=r"(a), "=r"(b) : "l"(v));
    lo = __uint_as_float(a); hi = __uint_as_float(b);
}

// ---------------- kernels ----------------
__global__ void zero_kernel() {
    int tid = threadIdx.x;
    for (int i = tid; i < B_*L_*C_; i += 256) g_sums[i] = 0.f;
    for (int i = tid; i < B_*L_;    i += 256) g_counts[i] = 0;
    if (tid == 0) { g_sum1 = 0.0; g_sum2 = 0.0; }
}

// conv_w [l][co][ci][1][3][3] -> g_pw [l][ci][k][co]  (co contiguous for f32x2 pairs)
__global__ void prepack_kernel(const float* __restrict__ w) {
    int i = blockIdx.x * 256 + threadIdx.x;
    if (i >= NCV*C_*C_*9) return;
    int k  = i % 9; int t = i / 9;
    int ci = t % C_; t /= C_;
    int co = t % C_; int l = t / C_;
    g_pw[((l*C_ + ci)*9 + k)*C_ + co] = w[((l*C_ + co)*C_ + ci)*9 + k];
}

// direct conv (1,3,3), pad(0,1,1), +bias, ReLU.  tile 32x8 px, all 64 co per thread
// src_sel: 0=ext_in, 1=g_bufA, 2=g_bufB ; dst_sel: 1=g_bufA, 2=g_bufB, 3=ext_out
__global__ void __launch_bounds__(256, 2)
conv_kernel(const float* __restrict__ ext_in, const float* __restrict__ bias,
            int layer, int src_sel, int dst_sel, float* __restrict__ ext_out) {
    extern __shared__ float smem[];
    float* tile = smem;               // 64*10*34 = 21760 floats
    float* wbuf = smem + C_*10*34;    // 8*9*64   = 4608 floats
    const float* in  = (src_sel == 0) ? ext_in : (src_sel == 1 ? g_bufA : g_bufB);
    float*       out = (dst_sel == 3) ? ext_out : (dst_sel == 1 ? g_bufA : g_bufB);
    const int tid = threadIdx.x;
    const int tx = tid & 31, ty = tid >> 5;
    const int bx = blockIdx.x * 32, by = blockIdx.y * 8;
    const int im = blockIdx.z;
    const int b = im >> 3, d = im & 7;
    const long ibase = ((long)b * C_ * D_ + d) * (H_*W_);

    // cooperative tile load with halo + zero padding (21760 = 85*256)
    for (int i = 0; i < 85; i++) {
        int li = i * 256 + tid;
        int ci = li / 340; int rem = li - ci * 340;
        int r = rem / 34;  int col = rem - r * 34;
        int gy = by - 1 + r, gx = bx - 1 + col;
        float v = 0.f;
        if ((unsigned)gy < 128u && (unsigned)gx < 128u)
            v = in[ibase + (long)ci * V_ + gy * W_ + gx];
        tile[ci * 340 + r * 34 + col] = v;
    }

    u64p acc[32];
    #pragma unroll
    for (int j = 0; j < 32; j++) acc[j] = 0ull;

    const float* wl = g_pw + (long)layer * (C_*9*C_);
    #pragma unroll 1
    for (int cc = 0; cc < C_; cc += 8) {
        __syncthreads();
        for (int i = tid; i < 8*9*64; i += 256) wbuf[i] = wl[cc*9*64 + i];
        __syncthreads();
        #pragma unroll 1
        for (int lci = 0; lci < 8; lci++) {
            const float* tl = tile + (cc + lci) * 340 + ty * 34 + tx;
            const u64p*  w2 = (const u64p*)(wbuf + lci * 9 * 64);
            #pragma unroll
            for (int k = 0; k < 9; k++) {
                const int dy = k / 3, dx = k % 3;
                u64p xx = pack2(tl[dy * 34 + dx]);
                const u64p* wk = w2 + k * 32;
                #pragma unroll
                for (int j = 0; j < 32; j++) acc[j] = ffma2(wk[j], xx, acc[j]);
            }
        }
    }

    const long obase = ibase + (long)(by + ty) * W_ + (bx + tx);
    #pragma unroll
    for (int j = 0; j < 32; j++) {
        float lo, hi; unpack2(acc[j], lo, hi);
        out[obase + (long)(2*j)   * V_] = fmaxf(lo + bias[2*j],   0.f);
        out[obase + (long)(2*j+1) * V_] = fmaxf(hi + bias[2*j+1], 0.f);
    }
}

__global__ void counts_kernel(const int* __restrict__ masks) {
    __shared__ int cnt[L_];
    int b = blockIdx.x, tid = threadIdx.x;
    if (tid < L_) cnt[tid] = 0;
    __syncthreads();
    const int* mp = masks + (long)b * V_;
    for (int v = tid; v < V_; v += 256) atomicAdd(&cnt[mp[v]], 1);
    __syncthreads();
    if (tid < L_) g_counts[b*L_ + tid] = cnt[tid];
}

// per-(b,c) label-sum histogram over the final conv features (= out x-region)
__global__ void seg_kernel(const float* __restrict__ X, const int* __restrict__ masks) {
    __shared__ float bins[L_];
    int b = blockIdx.x >> 6, c = blockIdx.x & 63;
    int tid = threadIdx.x;
    if (tid < L_) bins[tid] = 0.f;
    __syncthreads();
    const float* xp = X + ((long)(b*C_ + c)) * V_;
    const int*   mp = masks + (long)b * V_;
    for (int v = tid; v < V_; v += 256) atomicAdd(&bins[mp[v]], xp[v]);
    __syncthreads();
    if (tid < L_) g_sums[(b*L_ + tid)*C_ + c] = bins[tid];
}

// inst_features, mask_kernel linear, BatchNorm1d(KD), outputs + packed K
__global__ void head_kernel(const float* __restrict__ embed, const float* __restrict__ mkw,
                            const float* __restrict__ mkb,   const float* __restrict__ nkg,
                            const float* __restrict__ nkb,   float* __restrict__ out) {
    extern __shared__ float sm[];
    float* pk   = sm;                   // 240*64
    float* smu  = sm + B_*N_*KD_;       // 64
    float* sinv = smu + KD_;            // 64
    int tid = threadIdx.x;

    // pred_kernel = inst @ mk_w^T + mk_b   (inst computed inline)
    for (int e = tid; e < B_*N_*KD_; e += 256) {
        int kd = e & 63; int t = e >> 6; int n = t % N_; int b = t / N_;
        float acc = mkb[kd];
        if (n < 100) {
            int l = n + 1;
            float inv = 1.f / fmaxf((float)g_counts[b*L_ + l], 1.f);
            const float* srow = g_sums + (b*L_ + l)*C_;
            for (int c = 0; c < C_; c++) acc += (srow[c] * inv) * mkw[kd*C_ + c];
        } else {
            const float* er = embed + (n - 100)*C_;
            for (int c = 0; c < C_; c++) acc += er[c] * mkw[kd*C_ + c];
        }
        pk[e] = acc;
    }
    // inst_features output
    for (int e = tid; e < B_*N_*C_; e += 256) {
        int c = e & 63; int t = e >> 6; int n = t % N_; int b = t / N_;
        float v;
        if (n < 100) {
            int l = n + 1;
            v = g_sums[(b*L_ + l)*C_ + c] / fmaxf((float)g_counts[b*L_ + l], 1.f);
        } else v = embed[(n - 100)*C_ + c];
        out[OFF_INST + e] = v;
    }
    __syncthreads();
    if (tid < KD_) {
        float s = 0.f, s2 = 0.f;
        for (int r = 0; r < B_*N_; r++) { float v = pk[r*KD_ + tid]; s += v; s2 += v*v; }
        float mu  = s  / (float)(B_*N_);
        float var = s2 / (float)(B_*N_) - mu*mu;
        smu[tid]  = mu;
        sinv[tid] = 1.f / sqrtf(var + EPS_);
    }
    __syncthreads();
    for (int e = tid; e < B_*N_*KD_; e += 256) {
        int kd = e & 63; int t = e >> 6; int n = t % N_; int b = t / N_;
        float v = (pk[e] - smu[kd]) * sinv[kd] * nkg[kd] + nkb[kd];
        out[OFF_PK + e] = v;
        float2* kp = &g_kpack[(b*NP_ + (n >> 1))*KD_ + kd];
        if (n & 1) kp->y = v; else kp->x = v;
    }
}

// bmm [120,64]x[64,V] per batch. pass 0: sum/sumsq stats. pass 1: normalize+write.
__global__ void __launch_bounds__(256)
bmm_kernel(const float* __restrict__ M, float* __restrict__ out, int write_pass) {
    __shared__ u64p sK[NP_*KD_];     // 30720 B, [np][kd] pairs
    const int b = blockIdx.y;
    const int v = blockIdx.x * 256 + threadIdx.x;
    const u64p* Kg = (const u64p*)g_kpack + (long)b * NP_ * KD_;
    for (int i = threadIdx.x; i < NP_*KD_; i += 256) sK[i] = Kg[i];
    __syncthreads();

    const float* Mb = M + (long)b * C_ * V_;
    const float mu = g_mu2, sc = g_scale2, be = g_beta2;
    double tsum = 0.0, tsq = 0.0;

    #pragma unroll 1
    for (int half = 0; half < 2; half++) {
        u64p acc[30];
        #pragma unroll
        for (int j = 0; j < 30; j++) acc[j] = 0ull;
        #pragma unroll 4
        for (int k = 0; k < C_; k++) {
            u64p mm = pack2(Mb[(long)k * V_ + v]);
            #pragma unroll
            for (int j = 0; j < 30; j++)
                acc[j] = ffma2(sK[(half*30 + j)*KD_ + k], mm, acc[j]);
        }
        #pragma unroll
        for (int j = 0; j < 30; j++) {
            float lo, hi; unpack2(acc[j], lo, hi);
            if (write_pass) {
                int n = (half*30 + j) * 2;
                out[OFF_MASKS + ((long)(b*N_ + n))    * V_ + v] = (lo - mu)*sc + be;
                out[OFF_MASKS + ((long)(b*N_ + n + 1))* V_ + v] = (hi - mu)*sc + be;
            } else {
                tsum += (double)lo + (double)hi;
                tsq  += (double)lo*lo + (double)hi*hi;
            }
        }
    }
    if (!write_pass) {
        #pragma unroll
        for (int o = 16; o > 0; o >>= 1) {
            tsum += __shfl_down_sync(0xffffffffu, tsum, o);
            tsq  += __shfl_down_sync(0xffffffffu, tsq,  o);
        }
        if ((threadIdx.x & 31) == 0) {
            atomicAdd(&g_sum1, tsum);
            atomicAdd(&g_sum2, tsq);
        }
    }
}

__global__ void finalize_kernel(const float* __restrict__ nlg, const float* __restrict__ nlb) {
    double total = (double)B_ * N_ * V_;
    double mu  = g_sum1 / total;
    double var = g_sum2 / total - mu * mu;
    g_mu2    = (float)mu;
    g_scale2 = (float)((double)nlg[0] / sqrt(var + 1e-3));
    g_beta2  = nlb[0];
}

// ---------------- launch ----------------
extern "C" void kernel_launch(void* const* d_in, const int* in_sizes, int n_in,
                              void* d_out, int out_size) {
    const float* features      = (const float*)d_in[0];
    const float* mask_features = (const float*)d_in[1];
    const float* conv_w        = (const float*)d_in[2];
    const float* conv_b        = (const float*)d_in[3];
    const float* embed         = (const float*)d_in[4];
    const float* mk_w          = (const float*)d_in[5];
    const float* mk_b          = (const float*)d_in[6];
    const float* nkg           = (const float*)d_in[7];
    const float* nkb           = (const float*)d_in[8];
    const float* nlg           = (const float*)d_in[9];
    const float* nlb           = (const float*)d_in[10];
    const int*   init_masks    = (const int*)d_in[11];
    float* out = (float*)d_out;

    const int csm = (C_*10*34 + 8*9*64) * (int)sizeof(float);      // 105472
    const int hsm = (B_*N_*KD_ + 2*KD_) * (int)sizeof(float);      // 61952
    cudaFuncSetAttribute(conv_kernel, cudaFuncAttributeMaxDynamicSharedMemorySize, csm);
    cudaFuncSetAttribute(head_kernel, cudaFuncAttributeMaxDynamicSharedMemorySize, hsm);

    zero_kernel<<<1, 256>>>();
    prepack_kernel<<<(NCV*C_*C_*9 + 255)/256, 256>>>(conv_w);

    dim3 cgrid(W_/32, H_/8, B_*D_);
    conv_kernel<<<cgrid, 256, csm>>>(features, conv_b + 0*C_, 0, 0, 1, out);
    conv_kernel<<<cgrid, 256, csm>>>(features, conv_b + 1*C_, 1, 1, 2, out);
    conv_kernel<<<cgrid, 256, csm>>>(features, conv_b + 2*C_, 2, 2, 1, out);
    conv_kernel<<<cgrid, 256, csm>>>(features, conv_b + 3*C_, 3, 1, 3, out);  // -> x region

    counts_kernel<<<B_, 256>>>(init_masks);
    seg_kernel<<<B_*C_, 256>>>(out, init_masks);
    head_kernel<<<1, 256, hsm>>>(embed, mk_w, mk_b, nkg, nkb, out);

    dim3 ggrid(V_/256, B_);
    bmm_kernel<<<ggrid, 256>>>(mask_features, out, 0);
    finalize_kernel<<<1, 1>>>(nlg, nlb);
    bmm_kernel<<<ggrid, 256>>>(mask_features, out, 1);
}

// round 6
// speedup vs baseline: 1.2656x; 1.2656x over previous
#include <cuda_runtime.h>
#include <cstdint>

#define B_   2
#define C_   64
#define D_   8
#define H_   128
#define W_   128
#define V_   (D_*H_*W_)      // 131072
#define L_   101
#define NCV  4
#define KD_  64
#define NLM_ 20
#define N_   120
#define NP_  60              // n-pairs
#define EPS_ 1e-3f

// output layout (reference tuple order, flattened)
#define OFF_X     0L
#define NUM_X     (2L*64*8*128*128)          // 16777216
#define OFF_INST  (OFF_X + NUM_X)            // 16777216
#define NUM_INST  (2L*120*64)                // 15360
#define OFF_MASKS (OFF_INST + NUM_INST)      // 16792576
#define NUM_MASKS (2L*120*131072)            // 31457280
#define OFF_PK    (OFF_MASKS + NUM_MASKS)    // 48249856

typedef unsigned long long u64p;   // packed f32x2 carrier

// ---------------- device scratch (no allocations allowed) ----------------
__device__ float  g_bufA[B_*C_*V_];
__device__ float  g_bufB[B_*C_*V_];
__device__ float  g_pw[NCV*C_*9*C_];          // packed weights [l][ci][k][co]
__device__ float  g_sums[B_*L_*C_];
__device__ int    g_counts[B_*L_];
__device__ float  g_S[B_*C_*C_];              // per-b second moment of M
__device__ float  g_msum[B_*C_];              // per-b column sums of M
__device__ float  g_G[B_*KD_*KD_];            // per-b Gram of pred_kernel
__device__ float  g_ksum[B_*KD_];             // per-b column sums of pred_kernel
__device__ float  g_mu2, g_scale2, g_beta2;
__device__ float2 g_kpack[B_*NP_*KD_];        // (K[2np][kd], K[2np+1][kd])

// ---------------- packed f32x2 helpers (Blackwell) ----------------
__device__ __forceinline__ u64p ffma2(u64p a, u64p b, u64p c) {
    u64p d;
    asm("fma.rn.f32x2 %0, %1, %2, %3;" : "=l"(d) : "l"(a), "l"(b), "l"(c));
    return d;
}
__device__ __forceinline__ u64p pack2(float x) {
    u64p d; unsigned u = __float_as_uint(x);
    asm("mov.b64 %0, {%1, %1};" : "=l"(d) : "r"(u));
    return d;
}
__device__ __forceinline__ void unpack2(u64p v, float& lo, float& hi) {
    unsigned a, b;
    asm("mov.b64 {%0, %1}, %2;" : "=r"(a), "=r"(b) : "l"(v));
    lo = __uint_as_float(a); hi = __uint_as_float(b);
}

// ---------------- kernels ----------------
__global__ void zero_kernel() {
    int tid = threadIdx.x;
    for (int i = tid; i < B_*C_*C_; i += 256) g_S[i] = 0.f;
    for (int i = tid; i < B_*C_;    i += 256) g_msum[i] = 0.f;
}

// conv_w [l][co][ci][1][3][3] -> g_pw [l][ci][k][co]  (co contiguous for f32x2 pairs)
__global__ void prepack_kernel(const float* __restrict__ w) {
    int i = blockIdx.x * 256 + threadIdx.x;
    if (i >= NCV*C_*C_*9) return;
    int k  = i % 9; int t = i / 9;
    int ci = t % C_; t /= C_;
    int co = t % C_; int l = t / C_;
    g_pw[((l*C_ + ci)*9 + k)*C_ + co] = w[((l*C_ + co)*C_ + ci)*9 + k];
}

// direct conv (1,3,3), pad(0,1,1), +bias, ReLU.
// tile 32x8 px; each thread: 4 pixels (rows r0+2p) x 8 co-pairs (group g).
// Per (ci,k): 8 weight LDS.64 + 4 tile LDS.32 feed 32 FFMA2 (vs 33 LDS before).
__global__ void __launch_bounds__(256, 2)
conv_kernel(const float* __restrict__ ext_in, const float* __restrict__ bias,
            int layer, int src_sel, int dst_sel, float* __restrict__ ext_out) {
    extern __shared__ float smem[];
    float* tile = smem;               // 64*10*34 = 21760 floats
    float* wbuf = smem + C_*10*34;    // 8*9*64   = 4608 floats
    const float* in  = (src_sel == 0) ? ext_in : (src_sel == 1 ? g_bufA : g_bufB);
    float*       out = (dst_sel == 3) ? ext_out : (dst_sel == 1 ? g_bufA : g_bufB);
    const int tid = threadIdx.x;
    const int col = tid & 31;
    const int r0  = (tid >> 5) & 1;   // base row within pixel group
    const int g   = tid >> 6;         // co-pair group 0..3
    const int bx = blockIdx.x * 32, by = blockIdx.y * 8;
    const int im = blockIdx.z;
    const int b = im >> 3, d = im & 7;
    const long ibase = ((long)b * C_ * D_ + d) * (H_*W_);

    // cooperative tile load with halo + zero padding (21760 = 85*256)
    for (int i = 0; i < 85; i++) {
        int li = i * 256 + tid;
        int ci = li / 340; int rem = li - ci * 340;
        int r = rem / 34;  int c2 = rem - r * 34;
        int gy = by - 1 + r, gx = bx - 1 + c2;
        float v = 0.f;
        if ((unsigned)gy < 128u && (unsigned)gx < 128u)
            v = in[ibase + (long)ci * V_ + gy * W_ + gx];
        tile[ci * 340 + r * 34 + c2] = v;
    }

    u64p acc[32];                      // [p][j] = acc[p*8+j]
    #pragma unroll
    for (int j = 0; j < 32; j++) acc[j] = 0ull;

    const float* wl = g_pw + (long)layer * (C_*9*C_);
    #pragma unroll 1
    for (int cc = 0; cc < C_; cc += 8) {
        __syncthreads();
        for (int i = tid; i < 8*9*64; i += 256) wbuf[i] = wl[cc*9*64 + i];
        __syncthreads();
        #pragma unroll 1
        for (int lci = 0; lci < 8; lci++) {
            const float* tl = tile + (cc + lci) * 340 + r0 * 34 + col;
            const float* wb = wbuf + lci * 9 * 64;
            #pragma unroll
            for (int k = 0; k < 9; k++) {
                const int dy = k / 3, dx = k % 3;
                u64p t0 = pack2(tl[(0 + dy) * 34 + dx]);
                u64p t1 = pack2(tl[(2 + dy) * 34 + dx]);
                u64p t2 = pack2(tl[(4 + dy) * 34 + dx]);
                u64p t3 = pack2(tl[(6 + dy) * 34 + dx]);
                const u64p* wk = (const u64p*)(wb + k * 64) + g * 8;
                #pragma unroll
                for (int j = 0; j < 8; j++) {
                    u64p w = wk[j];
                    acc[0*8+j] = ffma2(w, t0, acc[0*8+j]);
                    acc[1*8+j] = ffma2(w, t1, acc[1*8+j]);
                    acc[2*8+j] = ffma2(w, t2, acc[2*8+j]);
                    acc[3*8+j] = ffma2(w, t3, acc[3*8+j]);
                }
            }
        }
    }

    #pragma unroll
    for (int p = 0; p < 4; p++) {
        const long ob = ibase + (long)(by + r0 + 2*p) * W_ + (bx + col);
        #pragma unroll
        for (int j = 0; j < 8; j++) {
            int co = 2 * (g * 8 + j);
            float lo, hi; unpack2(acc[p*8+j], lo, hi);
            out[ob + (long)co       * V_] = fmaxf(lo + bias[co],     0.f);
            out[ob + (long)(co + 1) * V_] = fmaxf(hi + bias[co + 1], 0.f);
        }
    }
}

// S_b = sum_v M M^T (64x64) and msum_b = sum_v M, per batch.  grid (64, 2).
#define SYRK_CH 2048
__global__ void __launch_bounds__(256)
syrk_kernel(const float* __restrict__ M) {
    __shared__ float t[64][65];
    const int b = blockIdx.y, tid = threadIdx.x;
    const int ti = tid >> 4, tj = tid & 15;     // 16x16 grid of 4x4 tiles
    const float* Mb = M + (long)b * C_ * V_;
    float acc[16];
    #pragma unroll
    for (int i = 0; i < 16; i++) acc[i] = 0.f;
    float csum = 0.f;
    const int vbase0 = blockIdx.x * SYRK_CH;

    for (int it = 0; it < SYRK_CH/64; it++) {
        int vb = vbase0 + it * 64;
        __syncthreads();
        #pragma unroll
        for (int q = 0; q < 16; q++) {
            int idx = q * 256 + tid;
            int c = idx >> 6, vv = idx & 63;
            t[c][vv] = Mb[(long)c * V_ + vb + vv];
        }
        __syncthreads();
        if (tid < 64) {
            float s = 0.f;
            #pragma unroll 8
            for (int vv = 0; vv < 64; vv++) s += t[tid][vv];
            csum += s;
        }
        #pragma unroll 2
        for (int vv = 0; vv < 64; vv++) {
            float a0 = t[ti*4+0][vv], a1 = t[ti*4+1][vv];
            float a2 = t[ti*4+2][vv], a3 = t[ti*4+3][vv];
            float b0 = t[tj*4+0][vv], b1 = t[tj*4+1][vv];
            float b2 = t[tj*4+2][vv], b3 = t[tj*4+3][vv];
            acc[0]  += a0*b0; acc[1]  += a0*b1; acc[2]  += a0*b2; acc[3]  += a0*b3;
            acc[4]  += a1*b0; acc[5]  += a1*b1; acc[6]  += a1*b2; acc[7]  += a1*b3;
            acc[8]  += a2*b0; acc[9]  += a2*b1; acc[10] += a2*b2; acc[11] += a2*b3;
            acc[12] += a3*b0; acc[13] += a3*b1; acc[14] += a3*b2; acc[15] += a3*b3;
        }
    }
    #pragma unroll
    for (int i = 0; i < 4; i++)
        #pragma unroll
        for (int j = 0; j < 4; j++)
            atomicAdd(&g_S[(b*C_ + ti*4 + i)*C_ + tj*4 + j], acc[i*4+j]);
    if (tid < 64) atomicAdd(&g_msum[b*C_ + tid], csum);
}

__global__ void counts_kernel(const int* __restrict__ masks) {
    __shared__ int cnt[L_];
    int b = blockIdx.x, tid = threadIdx.x;
    if (tid < L_) cnt[tid] = 0;
    __syncthreads();
    const int* mp = masks + (long)b * V_;
    for (int v = tid; v < V_; v += 256) atomicAdd(&cnt[mp[v]], 1);
    __syncthreads();
    if (tid < L_) g_counts[b*L_ + tid] = cnt[tid];
}

// per-(b,c) label-sum histogram over the final conv features (= out x-region)
__global__ void seg_kernel(const float* __restrict__ X, const int* __restrict__ masks) {
    __shared__ float bins[L_];
    int b = blockIdx.x >> 6, c = blockIdx.x & 63;
    int tid = threadIdx.x;
    if (tid < L_) bins[tid] = 0.f;
    __syncthreads();
    const float* xp = X + ((long)(b*C_ + c)) * V_;
    const int*   mp = masks + (long)b * V_;
    for (int v = tid; v < V_; v += 256) atomicAdd(&bins[mp[v]], xp[v]);
    __syncthreads();
    if (tid < L_) g_sums[(b*L_ + tid)*C_ + c] = bins[tid];
}

// inst_features, mask_kernel linear, BatchNorm1d(KD), outputs + packed K + Gram
__global__ void head_kernel(const float* __restrict__ embed, const float* __restrict__ mkw,
                            const float* __restrict__ mkb,   const float* __restrict__ nkg,
                            const float* __restrict__ nkb,   float* __restrict__ out) {
    extern __shared__ float sm[];
    float* pk   = sm;                   // 240*64
    float* smu  = sm + B_*N_*KD_;       // 64
    float* sinv = smu + KD_;            // 64
    int tid = threadIdx.x;

    for (int e = tid; e < B_*N_*KD_; e += 256) {
        int kd = e & 63; int t = e >> 6; int n = t % N_; int b = t / N_;
        float acc = mkb[kd];
        if (n < 100) {
            int l = n + 1;
            float inv = 1.f / fmaxf((float)g_counts[b*L_ + l], 1.f);
            const float* srow = g_sums + (b*L_ + l)*C_;
            for (int c = 0; c < C_; c++) acc += (srow[c] * inv) * mkw[kd*C_ + c];
        } else {
            const float* er = embed + (n - 100)*C_;
            for (int c = 0; c < C_; c++) acc += er[c] * mkw[kd*C_ + c];
        }
        pk[e] = acc;
    }
    for (int e = tid; e < B_*N_*C_; e += 256) {
        int c = e & 63; int t = e >> 6; int n = t % N_; int b = t / N_;
        float v;
        if (n < 100) {
            int l = n + 1;
            v = g_sums[(b*L_ + l)*C_ + c] / fmaxf((float)g_counts[b*L_ + l], 1.f);
        } else v = embed[(n - 100)*C_ + c];
        out[OFF_INST + e] = v;
    }
    __syncthreads();
    if (tid < KD_) {
        float s = 0.f, s2 = 0.f;
        for (int r = 0; r < B_*N_; r++) { float v = pk[r*KD_ + tid]; s += v; s2 += v*v; }
        float mu  = s  / (float)(B_*N_);
        float var = s2 / (float)(B_*N_) - mu*mu;
        smu[tid]  = mu;
        sinv[tid] = 1.f / sqrtf(var + EPS_);
    }
    __syncthreads();
    for (int e = tid; e < B_*N_*KD_; e += 256) {
        int kd = e & 63; int t = e >> 6; int n = t % N_; int b = t / N_;
        float v = (pk[e] - smu[kd]) * sinv[kd] * nkg[kd] + nkb[kd];
        out[OFF_PK + e] = v;
        pk[e] = v;                        // store normalized back for Gram
        float2* kp = &g_kpack[(b*NP_ + (n >> 1))*KD_ + kd];
        if (n & 1) kp->y = v; else kp->x = v;
    }
    __syncthreads();
    // Gram G_b = K^T K and column sums of K
    for (int e2 = tid; e2 < B_*KD_*KD_; e2 += 256) {
        int b = e2 >> 12; int c1 = (e2 >> 6) & 63; int c2 = e2 & 63;
        float s = 0.f;
        for (int n = 0; n < N_; n++)
            s += pk[(b*N_ + n)*KD_ + c1] * pk[(b*N_ + n)*KD_ + c2];
        g_G[e2] = s;
    }
    for (int e2 = tid; e2 < B_*KD_; e2 += 256) {
        int b = e2 >> 6, kd = e2 & 63;
        float s = 0.f;
        for (int n = 0; n < N_; n++) s += pk[(b*N_ + n)*KD_ + kd];
        g_ksum[e2] = s;
    }
}

// global BN stats from Gram identities: Sx = ksum.msum, Sxx = tr(G S)
__global__ void finalize_kernel(const float* __restrict__ nlg, const float* __restrict__ nlb) {
    __shared__ double r1[256], r2[256];
    int tid = threadIdx.x;
    double ex2 = 0.0, mu = 0.0;
    for (int i = tid; i < B_*KD_*KD_; i += 256) ex2 += (double)g_G[i] * (double)g_S[i];
    for (int i = tid; i < B_*KD_;     i += 256) mu  += (double)g_ksum[i] * (double)g_msum[i];
    r1[tid] = ex2; r2[tid] = mu;
    __syncthreads();
    for (int s = 128; s > 0; s >>= 1) {
        if (tid < s) { r1[tid] += r1[tid+s]; r2[tid] += r2[tid+s]; }
        __syncthreads();
    }
    if (tid == 0) {
        double tot = (double)B_ * N_ * V_;
        double m   = r2[0] / tot;
        double var = r1[0] / tot - m * m;
        g_mu2    = (float)m;
        g_scale2 = (float)((double)nlg[0] / sqrt(var + 1e-3));
        g_beta2  = nlb[0];
    }
}

// bmm [120,64]x[64,V] per batch, normalize + write (single pass)
__global__ void __launch_bounds__(256)
bmm_kernel(const float* __restrict__ M, float* __restrict__ out) {
    __shared__ u64p sK[NP_*KD_];     // 30720 B
    const int b = blockIdx.y;
    const int v = blockIdx.x * 256 + threadIdx.x;
    const u64p* Kg = (const u64p*)g_kpack + (long)b * NP_ * KD_;
    for (int i = threadIdx.x; i < NP_*KD_; i += 256) sK[i] = Kg[i];
    __syncthreads();

    const float* Mb = M + (long)b * C_ * V_;
    const float mu = g_mu2, sc = g_scale2, be = g_beta2;

    #pragma unroll 1
    for (int half = 0; half < 2; half++) {
        u64p acc[30];
        #pragma unroll
        for (int j = 0; j < 30; j++) acc[j] = 0ull;
        #pragma unroll 4
        for (int k = 0; k < C_; k++) {
            u64p mm = pack2(Mb[(long)k * V_ + v]);
            #pragma unroll
            for (int j = 0; j < 30; j++)
                acc[j] = ffma2(sK[(half*30 + j)*KD_ + k], mm, acc[j]);
        }
        #pragma unroll
        for (int j = 0; j < 30; j++) {
            float lo, hi; unpack2(acc[j], lo, hi);
            int n = (half*30 + j) * 2;
            out[OFF_MASKS + ((long)(b*N_ + n))     * V_ + v] = (lo - mu)*sc + be;
            out[OFF_MASKS + ((long)(b*N_ + n + 1)) * V_ + v] = (hi - mu)*sc + be;
        }
    }
}

// ---------------- launch ----------------
extern "C" void kernel_launch(void* const* d_in, const int* in_sizes, int n_in,
                              void* d_out, int out_size) {
    const float* features      = (const float*)d_in[0];
    const float* mask_features = (const float*)d_in[1];
    const float* conv_w        = (const float*)d_in[2];
    const float* conv_b        = (const float*)d_in[3];
    const float* embed         = (const float*)d_in[4];
    const float* mk_w          = (const float*)d_in[5];
    const float* mk_b          = (const float*)d_in[6];
    const float* nkg           = (const float*)d_in[7];
    const float* nkb           = (const float*)d_in[8];
    const float* nlg           = (const float*)d_in[9];
    const float* nlb           = (const float*)d_in[10];
    const int*   init_masks    = (const int*)d_in[11];
    float* out = (float*)d_out;

    const int csm = (C_*10*34 + 8*9*64) * (int)sizeof(float);      // 105472
    const int hsm = (B_*N_*KD_ + 2*KD_) * (int)sizeof(float);      // 61952
    cudaFuncSetAttribute(conv_kernel, cudaFuncAttributeMaxDynamicSharedMemorySize, csm);
    cudaFuncSetAttribute(head_kernel, cudaFuncAttributeMaxDynamicSharedMemorySize, hsm);

    zero_kernel<<<1, 256>>>();
    prepack_kernel<<<(NCV*C_*C_*9 + 255)/256, 256>>>(conv_w);

    dim3 sgrid(V_/SYRK_CH, B_);
    syrk_kernel<<<sgrid, 256>>>(mask_features);

    dim3 cgrid(W_/32, H_/8, B_*D_);
    conv_kernel<<<cgrid, 256, csm>>>(features, conv_b + 0*C_, 0, 0, 1, out);
    conv_kernel<<<cgrid, 256, csm>>>(features, conv_b + 1*C_, 1, 1, 2, out);
    conv_kernel<<<cgrid, 256, csm>>>(features, conv_b + 2*C_, 2, 2, 1, out);
    conv_kernel<<<cgrid, 256, csm>>>(features, conv_b + 3*C_, 3, 1, 3, out);  // -> x region

    counts_kernel<<<B_, 256>>>(init_masks);
    seg_kernel<<<B_*C_, 256>>>(out, init_masks);
    head_kernel<<<1, 256, hsm>>>(embed, mk_w, mk_b, nkg, nkb, out);
    finalize_kernel<<<1, 256>>>(nlg, nlb);

    dim3 ggrid(V_/256, B_);
    bmm_kernel<<<ggrid, 256>>>(mask_features, out);
}